// round 8
// baseline (speedup 1.0000x reference)
#include <cuda_runtime.h>
#include <cstdint>
#include <cstddef>

typedef unsigned long long ull;

#define T_STEPS 2048
#define HDIM 32
#define DIN 6
#define WARPS_PER_CTA 2
#define CHAINS_PER_WARP 2
#define CHUNK 64
#define NCHUNK (T_STEPS / CHUNK)

__device__ __forceinline__ ull fma2(ull a, ull b, ull c) {
    ull r;
    asm("fma.rn.f32x2 %0, %1, %2, %3;" : "=l"(r) : "l"(a), "l"(b), "l"(c));
    return r;
}
__device__ __forceinline__ ull add2(ull a, ull b) {
    ull r;
    asm("add.rn.f32x2 %0, %1, %2;" : "=l"(r) : "l"(a), "l"(b));
    return r;
}
__device__ __forceinline__ float hsum2(ull a) {
    float lo, hi;
    asm("mov.b64 {%0, %1}, %2;" : "=f"(lo), "=f"(hi) : "l"(a));
    return lo + hi;
}
__device__ __forceinline__ ull pack2(float lo, float hi) {
    ull r;
    asm("mov.b64 %0, {%1, %2};" : "=l"(r) : "f"(lo), "f"(hi));
    return r;
}
__device__ __forceinline__ float tanh_mufu(float x) {
    float r;
    asm("tanh.approx.f32 %0, %1;" : "=f"(r) : "f"(x));
    return r;
}

__device__ __forceinline__ uint32_t smem_u32(const void* p) {
    return (uint32_t)__cvta_generic_to_shared(p);
}
__device__ __forceinline__ void cp16(uint32_t saddr, const void* gaddr) {
    asm volatile("cp.async.cg.shared.global [%0], [%1], 16;" :: "r"(saddr), "l"(gaddr));
}
__device__ __forceinline__ void cp_commit() { asm volatile("cp.async.commit_group;"); }
__device__ __forceinline__ void cp_wait1()  { asm volatile("cp.async.wait_group 1;"); }

// stage one 1536B x-chunk for BOTH chains into shared (6 x 16B per lane), one group
__device__ __forceinline__ void stage_pair(float* dstA, const float* srcA,
                                           float* dstB, const float* srcB, int j) {
    uint32_t sA = smem_u32(dstA) + j * 16;
    const char* gA = (const char*)srcA + j * 16;
    cp16(sA,        gA);
    cp16(sA + 512,  gA + 512);
    cp16(sA + 1024, gA + 1024);
    uint32_t sB = smem_u32(dstB) + j * 16;
    const char* gB = (const char*)srcB + j * 16;
    cp16(sB,        gB);
    cp16(sB + 512,  gB + 512);
    cp16(sB + 1024, gB + 1024);
    cp_commit();
}

// RNN cell (layers 1,2): tanh( Wp . hin + Wr . hprev + bias ), bias folded into a0 init
__device__ __forceinline__ float cell(const ull (&wp)[16], const float* hin,
                                      const ull (&wr)[16], const float* hprev,
                                      ull biasp) {
    ull a0 = biasp, a1 = 0ull, a2 = 0ull, a3 = 0ull;
    const ulonglong2* hp = reinterpret_cast<const ulonglong2*>(hin);
    const ulonglong2* hr = reinterpret_cast<const ulonglong2*>(hprev);
#pragma unroll
    for (int p = 0; p < 8; p++) {
        ulonglong2 u = hp[p];           // LDS.128 broadcast
        a0 = fma2(u.x, wp[2 * p],     a0);
        a1 = fma2(u.y, wp[2 * p + 1], a1);
        ulonglong2 v = hr[p];
        a2 = fma2(v.x, wr[2 * p],     a2);
        a3 = fma2(v.y, wr[2 * p + 1], a3);
    }
    a0 = add2(add2(a0, a1), add2(a2, a3));
    return tanh_mufu(hsum2(a0));
}

// layer-0 cell: x-projection (D=6 -> 3 pairs) + recurrence, bias folded
__device__ __forceinline__ float cell0(const ull (&wx)[3], const float* xp,
                                       const ull (&wr)[16], const float* hprev,
                                       ull biasp) {
    const ull* xq = reinterpret_cast<const ull*>(xp);   // 8B-aligned pairs
    ull a0 = fma2(xq[0], wx[0], biasp);
    a0 = fma2(xq[1], wx[1], a0);
    a0 = fma2(xq[2], wx[2], a0);
    ull a1 = 0ull, a2 = 0ull;
    const ulonglong2* hr = reinterpret_cast<const ulonglong2*>(hprev);
#pragma unroll
    for (int p = 0; p < 8; p++) {
        ulonglong2 v = hr[p];
        a1 = fma2(v.x, wr[2 * p],     a1);
        a2 = fma2(v.y, wr[2 * p + 1], a2);
    }
    a0 = add2(a0, add2(a1, a2));
    return tanh_mufu(hsum2(a0));
}

__global__ void __launch_bounds__(WARPS_PER_CTA * 32, 1)
rnn3_dual_kernel(const float* __restrict__ x,
                 const float* __restrict__ Wih0,
                 const float* __restrict__ WihR,
                 const float* __restrict__ Whh,
                 const float* __restrict__ bih,
                 const float* __restrict__ bhh,
                 const float* __restrict__ fcw,
                 const float* __restrict__ fcb,
                 float* __restrict__ out) {
    // [warp][chain][layer][parity][h]
    __shared__ __align__(16) float hb[WARPS_PER_CTA][2][3][2][HDIM];
    // [warp][chain][buf][CHUNK*DIN]
    __shared__ __align__(16) float xs[WARPS_PER_CTA][2][2][CHUNK * DIN];

    const int tid = threadIdx.x;
    const int w = tid >> 5;
    const int j = tid & 31;
    const int chain0 = (blockIdx.x * WARPS_PER_CTA + w) * CHAINS_PER_WARP;

    // zero h state (both chains, both parities)
    for (int q = tid; q < WARPS_PER_CTA * 2 * 3 * 2 * HDIM; q += WARPS_PER_CTA * 32)
        (&hb[0][0][0][0][0])[q] = 0.0f;
    __syncthreads();

    // ---- weights in registers as packed f32x2 pairs (shared by both chains) ----
    ull wx0[3], wr0[16], wp1[16], wr1[16], wp2[16], wr2[16];
    {
        const ull* q = reinterpret_cast<const ull*>(Wih0 + j * DIN);
        wx0[0] = q[0]; wx0[1] = q[1]; wx0[2] = q[2];
    }
    {
        const ull* q0 = reinterpret_cast<const ull*>(Whh  + (0 * HDIM + j) * HDIM);
        const ull* q1 = reinterpret_cast<const ull*>(Whh  + (1 * HDIM + j) * HDIM);
        const ull* q2 = reinterpret_cast<const ull*>(Whh  + (2 * HDIM + j) * HDIM);
        const ull* p1 = reinterpret_cast<const ull*>(WihR + (0 * HDIM + j) * HDIM);
        const ull* p2 = reinterpret_cast<const ull*>(WihR + (1 * HDIM + j) * HDIM);
#pragma unroll
        for (int k = 0; k < 16; k++) {
            wr0[k] = q0[k]; wr1[k] = q1[k]; wr2[k] = q2[k];
            wp1[k] = p1[k]; wp2[k] = p2[k];
        }
    }
    const ull bp0 = pack2(bih[0 * HDIM + j] + bhh[0 * HDIM + j], 0.0f);
    const ull bp1 = pack2(bih[1 * HDIM + j] + bhh[1 * HDIM + j], 0.0f);
    const ull bp2 = pack2(bih[2 * HDIM + j] + bhh[2 * HDIM + j], 0.0f);

    float* h0A = &hb[w][0][0][0][0];
    float* h1A = &hb[w][0][1][0][0];
    float* h2A = &hb[w][0][2][0][0];
    float* h0B = &hb[w][1][0][0][0];
    float* h1B = &hb[w][1][1][0][0];
    float* h2B = &hb[w][1][2][0][0];

    // ---- x staging via cp.async for both chains ----
    const float* gxA = x + (size_t)chain0 * (T_STEPS * DIN);
    const float* gxB = gxA + (size_t)(T_STEPS * DIN);
    float* xbA[2] = { &xs[w][0][0][0], &xs[w][0][1][0] };
    float* xbB[2] = { &xs[w][1][0][0], &xs[w][1][1][0] };

    stage_pair(xbA[0], gxA, xbB[0], gxB, j);                               // group: chunk0
    stage_pair(xbA[1], gxA + CHUNK * DIN, xbB[1], gxB + CHUNK * DIN, j);   // group: chunk1
    cp_wait1();                                                            // chunk0 ready
    __syncwarp();

    float h2lastA = 0.0f, h2lastB = 0.0f;

    // skewed iteration for both chains: L0 @ t, L1 @ t-1, L2 @ t-2.
    // Six compact cells; A/B pairs are independent -> pairwise ILP.
    auto iter = [&](int pw, const float* xpA, const float* xpB) {
        const int pr = pw ^ 1;
        float n0A = cell0(wx0, xpA,             wr0, h0A + pr * HDIM, bp0);
        float n0B = cell0(wx0, xpB,             wr0, h0B + pr * HDIM, bp0);
        float n1A = cell (wp1, h0A + pr * HDIM, wr1, h1A + pw * HDIM, bp1);
        float n1B = cell (wp1, h0B + pr * HDIM, wr1, h1B + pw * HDIM, bp1);
        float n2A = cell (wp2, h1A + pw * HDIM, wr2, h2A + pr * HDIM, bp2);
        float n2B = cell (wp2, h1B + pw * HDIM, wr2, h2B + pr * HDIM, bp2);
        h0A[pw * HDIM + j] = n0A;
        h1A[pr * HDIM + j] = n1A;
        h2A[pw * HDIM + j] = n2A;
        h0B[pw * HDIM + j] = n0B;
        h1B[pr * HDIM + j] = n1B;
        h2B[pw * HDIM + j] = n2B;
        __syncwarp();
    };

    // ---- prologue peels (fill the skew pipeline) ----
    {   // i = 0: only L0(0); h0[-1]=0 (parity 1 zeroed)
        float nA = cell0(wx0, xbA[0] + 0 * DIN, wr0, h0A + HDIM, bp0);
        float nB = cell0(wx0, xbB[0] + 0 * DIN, wr0, h0B + HDIM, bp0);
        h0A[j] = nA;
        h0B[j] = nB;
        __syncwarp();
    }
    {   // i = 1: L0(1) + L1(0); h1[-1]=0 (parity 1 zeroed)
        float n0A = cell0(wx0, xbA[0] + 1 * DIN, wr0, h0A, bp0);
        float n0B = cell0(wx0, xbB[0] + 1 * DIN, wr0, h0B, bp0);
        float n1A = cell (wp1, h0A, wr1, h1A + HDIM, bp1);
        float n1B = cell (wp1, h0B, wr1, h1B + HDIM, bp1);
        h0A[HDIM + j] = n0A;
        h1A[j] = n1A;
        h0B[HDIM + j] = n0B;
        h1B[j] = n1B;
        __syncwarp();
    }

    // ---- main loop: i = 2 .. 2047 ----
#pragma unroll 1
    for (int c = 0; c < NCHUNK; c++) {
        const float* xrA = xbA[c & 1];
        const float* xrB = xbB[c & 1];
        const int s0 = (c == 0) ? 2 : 0;
#pragma unroll 1
        for (int s = s0; s < CHUNK; s += 2) {
            iter(0, xrA + s * DIN,       xrB + s * DIN);
            iter(1, xrA + (s + 1) * DIN, xrB + (s + 1) * DIN);
        }
        // prefetch chunk c+2 into the buffer just consumed, then wait for c+1
        if (c + 2 < NCHUNK)
            stage_pair(xbA[c & 1], gxA + (c + 2) * CHUNK * DIN,
                       xbB[c & 1], gxB + (c + 2) * CHUNK * DIN, j);
        else
            cp_commit();
        cp_wait1();
        __syncwarp();
    }

    // ---- epilogue peels ----
    {   // L1(2047) + L2(2046)
        float n1A = cell(wp1, h0A + HDIM, wr1, h1A,        bp1);
        float n1B = cell(wp1, h0B + HDIM, wr1, h1B,        bp1);
        float n2A = cell(wp2, h1A,        wr2, h2A + HDIM, bp2);
        float n2B = cell(wp2, h1B,        wr2, h2B + HDIM, bp2);
        h1A[HDIM + j] = n1A;
        h2A[j] = n2A;
        h1B[HDIM + j] = n1B;
        h2B[j] = n2B;
        __syncwarp();
    }
    {   // L2(2047) -> final hidden states in registers
        h2lastA = cell(wp2, h1A + HDIM, wr2, h2A, bp2);
        h2lastB = cell(wp2, h1B + HDIM, wr2, h2B, bp2);
    }

    // ---- FC head for both chains ----
#pragma unroll
    for (int cix = 0; cix < 2; cix++) {
        float hl = (cix == 0) ? h2lastA : h2lastB;
        float s0v = hl * fcw[0 * HDIM + j];
        float s1v = hl * fcw[1 * HDIM + j];
        float s2v = hl * fcw[2 * HDIM + j];
        float s3v = hl * fcw[3 * HDIM + j];
        float s4v = hl * fcw[4 * HDIM + j];
        float s5v = hl * fcw[5 * HDIM + j];
#pragma unroll
        for (int off = 16; off; off >>= 1) {
            s0v += __shfl_xor_sync(0xffffffffu, s0v, off);
            s1v += __shfl_xor_sync(0xffffffffu, s1v, off);
            s2v += __shfl_xor_sync(0xffffffffu, s2v, off);
            s3v += __shfl_xor_sync(0xffffffffu, s3v, off);
            s4v += __shfl_xor_sync(0xffffffffu, s4v, off);
            s5v += __shfl_xor_sync(0xffffffffu, s5v, off);
        }
        float v = s0v;
        if (j == 1) v = s1v;
        if (j == 2) v = s2v;
        if (j == 3) v = s3v;
        if (j == 4) v = s4v;
        if (j == 5) v = s5v;
        if (j < 6) out[(chain0 + cix) * 6 + j] = v + fcb[j];
    }
}

extern "C" void kernel_launch(void* const* d_in, const int* in_sizes, int n_in,
                              void* d_out, int out_size) {
    const float* x    = (const float*)d_in[0];
    const float* Wih0 = (const float*)d_in[1];
    const float* WihR = (const float*)d_in[2];
    const float* Whh  = (const float*)d_in[3];
    const float* bih  = (const float*)d_in[4];
    const float* bhh  = (const float*)d_in[5];
    const float* fcw  = (const float*)d_in[6];
    const float* fcb  = (const float*)d_in[7];

    const int B = in_sizes[0] / (T_STEPS * DIN);   // 512
    const int grid = B / (WARPS_PER_CTA * CHAINS_PER_WARP);   // 128
    rnn3_dual_kernel<<<grid, WARPS_PER_CTA * 32>>>(
        x, Wih0, WihR, Whh, bih, bhh, fcw, fcb, (float*)d_out);
}

// round 9
// speedup vs baseline: 1.5505x; 1.5505x over previous
#include <cuda_runtime.h>
#include <cstdint>
#include <cstddef>

typedef unsigned long long ull;

#define T_STEPS 2048
#define HDIM 32
#define DIN 6
#define WARPS_PER_CTA 4
#define CHUNK 64
#define NCHUNK (T_STEPS / CHUNK)

__device__ __forceinline__ ull fma2(ull a, ull b, ull c) {
    ull r;
    asm("fma.rn.f32x2 %0, %1, %2, %3;" : "=l"(r) : "l"(a), "l"(b), "l"(c));
    return r;
}
__device__ __forceinline__ ull add2(ull a, ull b) {
    ull r;
    asm("add.rn.f32x2 %0, %1, %2;" : "=l"(r) : "l"(a), "l"(b));
    return r;
}
__device__ __forceinline__ float hsum2(ull a) {
    float lo, hi;
    asm("mov.b64 {%0, %1}, %2;" : "=f"(lo), "=f"(hi) : "l"(a));
    return lo + hi;
}
__device__ __forceinline__ ull pack2(float lo, float hi) {
    ull r;
    asm("mov.b64 %0, {%1, %2};" : "=l"(r) : "f"(lo), "f"(hi));
    return r;
}
__device__ __forceinline__ float tanh_mufu(float x) {
    float r;
    asm("tanh.approx.f32 %0, %1;" : "=f"(r) : "f"(x));
    return r;
}

__device__ __forceinline__ uint32_t smem_u32(const void* p) {
    return (uint32_t)__cvta_generic_to_shared(p);
}
__device__ __forceinline__ void cp16(uint32_t saddr, const void* gaddr) {
    asm volatile("cp.async.cg.shared.global [%0], [%1], 16;" :: "r"(saddr), "l"(gaddr));
}
__device__ __forceinline__ void cp_commit() { asm volatile("cp.async.commit_group;"); }
__device__ __forceinline__ void cp_wait1()  { asm volatile("cp.async.wait_group 1;"); }

// stage one 1536B x-chunk into shared (3 x 16B per lane)
__device__ __forceinline__ void stage_chunk(float* dst, const float* src, int j) {
    uint32_t s = smem_u32(dst) + j * 16;
    const char* g = (const char*)src + j * 16;
    cp16(s,        g);
    cp16(s + 512,  g + 512);
    cp16(s + 1024, g + 1024);
    cp_commit();
}

// ---- peel-only helpers (cold) ----
__device__ __forceinline__ float cell(const ull (&wp)[16], const float* hin,
                                      const ull (&wr)[16], const float* hprev,
                                      ull biasp) {
    ull a0 = biasp, a1 = 0ull, a2 = 0ull, a3 = 0ull;
    const ulonglong2* hp = reinterpret_cast<const ulonglong2*>(hin);
    const ulonglong2* hr = reinterpret_cast<const ulonglong2*>(hprev);
#pragma unroll
    for (int p = 0; p < 8; p++) {
        ulonglong2 u = hp[p];
        a0 = fma2(u.x, wp[2 * p],     a0);
        a1 = fma2(u.y, wp[2 * p + 1], a1);
        ulonglong2 v = hr[p];
        a2 = fma2(v.x, wr[2 * p],     a2);
        a3 = fma2(v.y, wr[2 * p + 1], a3);
    }
    a0 = add2(add2(a0, a1), add2(a2, a3));
    return tanh_mufu(hsum2(a0));
}
__device__ __forceinline__ float cell0(const ull (&wx)[3], const float* xp,
                                       const ull (&wr)[16], const float* hprev,
                                       ull biasp) {
    const ull* xq = reinterpret_cast<const ull*>(xp);
    ull a0 = fma2(xq[0], wx[0], biasp);
    a0 = fma2(xq[1], wx[1], a0);
    a0 = fma2(xq[2], wx[2], a0);
    ull a1 = 0ull, a2 = 0ull;
    const ulonglong2* hr = reinterpret_cast<const ulonglong2*>(hprev);
#pragma unroll
    for (int p = 0; p < 8; p++) {
        ulonglong2 v = hr[p];
        a1 = fma2(v.x, wr[2 * p],     a1);
        a2 = fma2(v.y, wr[2 * p + 1], a2);
    }
    a0 = add2(a0, add2(a1, a2));
    return tanh_mufu(hsum2(a0));
}

__global__ void __launch_bounds__(WARPS_PER_CTA * 32, 1)
rnn3_fused_kernel(const float* __restrict__ x,
                  const float* __restrict__ Wih0,
                  const float* __restrict__ WihR,
                  const float* __restrict__ Whh,
                  const float* __restrict__ bih,
                  const float* __restrict__ bhh,
                  const float* __restrict__ fcw,
                  const float* __restrict__ fcb,
                  float* __restrict__ out) {
    __shared__ __align__(16) float hb[WARPS_PER_CTA][3][2][HDIM];       // [warp][layer][parity][h]
    __shared__ __align__(16) float xs[WARPS_PER_CTA][2][CHUNK * DIN];   // x staging, double buffered

    const int tid = threadIdx.x;
    const int w = tid >> 5;
    const int j = tid & 31;
    const int b = blockIdx.x * WARPS_PER_CTA + w;

    // zero h state (both parities)
    for (int q = tid; q < WARPS_PER_CTA * 3 * 2 * HDIM; q += WARPS_PER_CTA * 32)
        (&hb[0][0][0][0])[q] = 0.0f;
    __syncthreads();

    // ---- weights in registers as packed f32x2 pairs ----
    ull wx0[3], wr0[16], wp1[16], wr1[16], wp2[16], wr2[16];
    {
        const ull* q = reinterpret_cast<const ull*>(Wih0 + j * DIN);
        wx0[0] = q[0]; wx0[1] = q[1]; wx0[2] = q[2];
    }
    {
        const ull* q0 = reinterpret_cast<const ull*>(Whh  + (0 * HDIM + j) * HDIM);
        const ull* q1 = reinterpret_cast<const ull*>(Whh  + (1 * HDIM + j) * HDIM);
        const ull* q2 = reinterpret_cast<const ull*>(Whh  + (2 * HDIM + j) * HDIM);
        const ull* p1 = reinterpret_cast<const ull*>(WihR + (0 * HDIM + j) * HDIM);
        const ull* p2 = reinterpret_cast<const ull*>(WihR + (1 * HDIM + j) * HDIM);
#pragma unroll
        for (int k = 0; k < 16; k++) {
            wr0[k] = q0[k]; wr1[k] = q1[k]; wr2[k] = q2[k];
            wp1[k] = p1[k]; wp2[k] = p2[k];
        }
    }
    const ull bp0 = pack2(bih[0 * HDIM + j] + bhh[0 * HDIM + j], 0.0f);
    const ull bp1 = pack2(bih[1 * HDIM + j] + bhh[1 * HDIM + j], 0.0f);
    const ull bp2 = pack2(bih[2 * HDIM + j] + bhh[2 * HDIM + j], 0.0f);

    float* h0 = &hb[w][0][0][0];
    float* h1 = &hb[w][1][0][0];
    float* h2 = &hb[w][2][0][0];

    // ---- x staging via cp.async: chunk0 + chunk1 in flight ----
    const float* gx = x + (size_t)b * (T_STEPS * DIN);
    float* xb[2] = { &xs[w][0][0], &xs[w][1][0] };

    stage_chunk(xb[0], gx, j);                         // group: chunk0
    stage_chunk(xb[1], gx + CHUNK * DIN, j);           // group: chunk1
    cp_wait1();                                        // chunk0 ready
    __syncwarp();

    float h2last = 0.0f;

    // Fused skewed iteration, memory-ordered: ALL loads (block-staged with
    // >=32cyc of fma2 cover each) -> all FMAs -> stores -> syncwarp.
    // No LDS ever follows an STS, so ptxas's may-alias fence costs nothing.
    auto iter = [&](int pw, const float* xp) {
        const int pr = pw ^ 1;
        const ulonglong2* H0 = reinterpret_cast<const ulonglong2*>(h0 + pr * HDIM);
        const ulonglong2* H1 = reinterpret_cast<const ulonglong2*>(h1 + pw * HDIM);
        const ulonglong2* H2 = reinterpret_cast<const ulonglong2*>(h2 + pr * HDIM);
        const ull* xq = reinterpret_cast<const ull*>(xp);

        // -- load H0 (8 x LDS.128) --
        ulonglong2 u0[8];
#pragma unroll
        for (int p = 0; p < 8; p++) u0[p] = H0[p];

        // -- L0: x-projection + recurrence (19 fma2) --
        ull ax = fma2(xq[0], wx0[0], bp0);
        ax = fma2(xq[1], wx0[1], ax);
        ax = fma2(xq[2], wx0[2], ax);
        ull a1 = 0ull, a2 = 0ull;
#pragma unroll
        for (int p = 0; p < 8; p++) {
            a1 = fma2(u0[p].x, wr0[2 * p],     a1);
            a2 = fma2(u0[p].y, wr0[2 * p + 1], a2);
        }

        // -- load H1 (covered by L0's 19 fma2 ~= 38 cyc) --
        ulonglong2 u1[8];
#pragma unroll
        for (int p = 0; p < 8; p++) u1[p] = H1[p];

        // -- L1 part A: wp1 . h0  (consumes u0; covers H1) --
        ull d0 = bp1, d1 = 0ull;
#pragma unroll
        for (int p = 0; p < 8; p++) {
            d0 = fma2(u0[p].x, wp1[2 * p],     d0);
            d1 = fma2(u0[p].y, wp1[2 * p + 1], d1);
        }

        // -- load H2 (covered by L1a + L1b ~= 64 cyc) --
        ulonglong2 u2[8];
#pragma unroll
        for (int p = 0; p < 8; p++) u2[p] = H2[p];

        // -- L1 part B: wr1 . h1 --
        ull d2 = 0ull, d3 = 0ull;
#pragma unroll
        for (int p = 0; p < 8; p++) {
            d2 = fma2(u1[p].x, wr1[2 * p],     d2);
            d3 = fma2(u1[p].y, wr1[2 * p + 1], d3);
        }
        float n0 = tanh_mufu(hsum2(add2(ax, add2(a1, a2))));   // a-chains long done

        // -- L2 part A: wp2 . h1 --
        ull e0 = bp2, e1 = 0ull;
#pragma unroll
        for (int p = 0; p < 8; p++) {
            e0 = fma2(u1[p].x, wp2[2 * p],     e0);
            e1 = fma2(u1[p].y, wp2[2 * p + 1], e1);
        }
        float n1 = tanh_mufu(hsum2(add2(add2(d0, d1), add2(d2, d3))));

        // -- L2 part B: wr2 . h2 --
        ull e2 = 0ull, e3 = 0ull;
#pragma unroll
        for (int p = 0; p < 8; p++) {
            e2 = fma2(u2[p].x, wr2[2 * p],     e2);
            e3 = fma2(u2[p].y, wr2[2 * p + 1], e3);
        }
        float n2 = tanh_mufu(hsum2(add2(add2(e0, e1), add2(e2, e3))));

        // -- stores last --
        h0[pw * HDIM + j] = n0;
        h1[pr * HDIM + j] = n1;
        h2[pw * HDIM + j] = n2;
        __syncwarp();
    };

    // ---- prologue peels (fill the skew pipeline) ----
    {   // i = 0: only L0(0); h0[-1]=0 (parity 1 zeroed)
        float n0 = cell0(wx0, xb[0] + 0 * DIN, wr0, h0 + HDIM, bp0);
        h0[j] = n0;
        __syncwarp();
    }
    {   // i = 1: L0(1) + L1(0); h1[-1]=0 (parity 1 zeroed)
        float n0 = cell0(wx0, xb[0] + 1 * DIN, wr0, h0, bp0);
        float n1 = cell (wp1, h0, wr1, h1 + HDIM, bp1);
        h0[HDIM + j] = n0;
        h1[j] = n1;
        __syncwarp();
    }

    // ---- main loop: i = 2 .. 2047 ----
#pragma unroll 1
    for (int c = 0; c < NCHUNK; c++) {
        const float* xrow = xb[c & 1];
        const int s0 = (c == 0) ? 2 : 0;
#pragma unroll 1
        for (int s = s0; s < CHUNK; s += 2) {
            iter(0, xrow + s * DIN);            // even global t
            iter(1, xrow + (s + 1) * DIN);      // odd global t
        }
        // prefetch chunk c+2 into the buffer just consumed, then wait for c+1
        if (c + 2 < NCHUNK)
            stage_chunk(xb[c & 1], gx + (c + 2) * CHUNK * DIN, j);
        else
            cp_commit();                        // keep group accounting uniform
        cp_wait1();                             // chunk c+1 resident
        __syncwarp();
    }

    // ---- epilogue peels ----
    {   // L1(2047) + L2(2046)
        float n1 = cell(wp1, h0 + HDIM, wr1, h1,        bp1);
        float n2 = cell(wp2, h1,        wr2, h2 + HDIM, bp2);
        h1[HDIM + j] = n1;
        h2[j] = n2;
        __syncwarp();
    }
    {   // L2(2047) -> final hidden state, keep in register
        h2last = cell(wp2, h1 + HDIM, wr2, h2, bp2);
    }

    // ---- FC head: out[b,c] = sum_j h2last_j * fcw[c,j] + fcb[c] ----
    float s0v = h2last * fcw[0 * HDIM + j];
    float s1v = h2last * fcw[1 * HDIM + j];
    float s2v = h2last * fcw[2 * HDIM + j];
    float s3v = h2last * fcw[3 * HDIM + j];
    float s4v = h2last * fcw[4 * HDIM + j];
    float s5v = h2last * fcw[5 * HDIM + j];
#pragma unroll
    for (int off = 16; off; off >>= 1) {
        s0v += __shfl_xor_sync(0xffffffffu, s0v, off);
        s1v += __shfl_xor_sync(0xffffffffu, s1v, off);
        s2v += __shfl_xor_sync(0xffffffffu, s2v, off);
        s3v += __shfl_xor_sync(0xffffffffu, s3v, off);
        s4v += __shfl_xor_sync(0xffffffffu, s4v, off);
        s5v += __shfl_xor_sync(0xffffffffu, s5v, off);
    }
    float v = s0v;
    if (j == 1) v = s1v;
    if (j == 2) v = s2v;
    if (j == 3) v = s3v;
    if (j == 4) v = s4v;
    if (j == 5) v = s5v;
    if (j < 6) out[b * 6 + j] = v + fcb[j];
}

extern "C" void kernel_launch(void* const* d_in, const int* in_sizes, int n_in,
                              void* d_out, int out_size) {
    const float* x    = (const float*)d_in[0];
    const float* Wih0 = (const float*)d_in[1];
    const float* WihR = (const float*)d_in[2];
    const float* Whh  = (const float*)d_in[3];
    const float* bih  = (const float*)d_in[4];
    const float* bhh  = (const float*)d_in[5];
    const float* fcw  = (const float*)d_in[6];
    const float* fcb  = (const float*)d_in[7];

    const int B = in_sizes[0] / (T_STEPS * DIN);   // 512
    rnn3_fused_kernel<<<B / WARPS_PER_CTA, WARPS_PER_CTA * 32>>>(
        x, Wih0, WihR, Whh, bih, bhh, fcw, fcb, (float*)d_out);
}

// round 10
// speedup vs baseline: 1.9323x; 1.2462x over previous
#include <cuda_runtime.h>
#include <cstdint>
#include <cstddef>

typedef unsigned long long ull;

#define T_STEPS 2048
#define HDIM 32
#define DIN 6
#define WARPS_PER_CTA 4
#define CHUNK 64
#define NCHUNK (T_STEPS / CHUNK)

// Compiler-only memory fence: stops nvcc/ptxas from reordering smem ops across
// it (cross-lane visibility), but emits NO instruction. HW processes a warp's
// shared-memory ops in issue order, so no WARPSYNC is needed on convergent code.
#define CBAR() asm volatile("" ::: "memory")

__device__ __forceinline__ ull fma2(ull a, ull b, ull c) {
    ull r;
    asm("fma.rn.f32x2 %0, %1, %2, %3;" : "=l"(r) : "l"(a), "l"(b), "l"(c));
    return r;
}
__device__ __forceinline__ ull add2(ull a, ull b) {
    ull r;
    asm("add.rn.f32x2 %0, %1, %2;" : "=l"(r) : "l"(a), "l"(b));
    return r;
}
__device__ __forceinline__ float hsum2(ull a) {
    float lo, hi;
    asm("mov.b64 {%0, %1}, %2;" : "=f"(lo), "=f"(hi) : "l"(a));
    return lo + hi;
}
__device__ __forceinline__ ull pack2(float lo, float hi) {
    ull r;
    asm("mov.b64 %0, {%1, %2};" : "=l"(r) : "f"(lo), "f"(hi));
    return r;
}
// single-instruction MUFU.TANH
__device__ __forceinline__ float tanh_mufu(float x) {
    float r;
    asm("tanh.approx.f32 %0, %1;" : "=f"(r) : "f"(x));
    return r;
}

// RNN cell (layers 1,2): tanh( Wp . hin + Wr . hprev + bias ), bias folded into a0 init
__device__ __forceinline__ float cell(const ull (&wp)[16], const float* hin,
                                      const ull (&wr)[16], const float* hprev,
                                      ull biasp) {
    ull a0 = biasp, a1 = 0ull, a2 = 0ull, a3 = 0ull;
    const ulonglong2* hp = reinterpret_cast<const ulonglong2*>(hin);
    const ulonglong2* hr = reinterpret_cast<const ulonglong2*>(hprev);
#pragma unroll
    for (int p = 0; p < 8; p++) {
        ulonglong2 u = hp[p];           // LDS.128 broadcast: h[4p..4p+3]
        a0 = fma2(u.x, wp[2 * p],     a0);
        a1 = fma2(u.y, wp[2 * p + 1], a1);
        ulonglong2 v = hr[p];
        a2 = fma2(v.x, wr[2 * p],     a2);
        a3 = fma2(v.y, wr[2 * p + 1], a3);
    }
    a0 = add2(add2(a0, a1), add2(a2, a3));
    return tanh_mufu(hsum2(a0));
}

// layer-0 cell: x-projection (D=6 -> 3 pairs) + recurrence, bias folded
__device__ __forceinline__ float cell0(const ull (&wx)[3], const float* xp,
                                       const ull (&wr)[16], const float* hprev,
                                       ull biasp) {
    const ull* xq = reinterpret_cast<const ull*>(xp);   // 8B-aligned pairs
    ull a0 = fma2(xq[0], wx[0], biasp);
    a0 = fma2(xq[1], wx[1], a0);
    a0 = fma2(xq[2], wx[2], a0);
    ull a1 = 0ull, a2 = 0ull;
    const ulonglong2* hr = reinterpret_cast<const ulonglong2*>(hprev);
#pragma unroll
    for (int p = 0; p < 8; p++) {
        ulonglong2 v = hr[p];
        a1 = fma2(v.x, wr[2 * p],     a1);
        a2 = fma2(v.y, wr[2 * p + 1], a2);
    }
    a0 = add2(a0, add2(a1, a2));
    return tanh_mufu(hsum2(a0));
}

__global__ void __launch_bounds__(WARPS_PER_CTA * 32, 1)
rnn3_fused_kernel(const float* __restrict__ x,
                  const float* __restrict__ Wih0,
                  const float* __restrict__ WihR,
                  const float* __restrict__ Whh,
                  const float* __restrict__ bih,
                  const float* __restrict__ bhh,
                  const float* __restrict__ fcw,
                  const float* __restrict__ fcb,
                  float* __restrict__ out) {
    __shared__ __align__(16) float hb[WARPS_PER_CTA][3][2][HDIM];       // [warp][layer][parity][h]
    __shared__ __align__(16) float xs[WARPS_PER_CTA][2][CHUNK * DIN];   // x staging, double buffered

    const int tid = threadIdx.x;
    const int w = tid >> 5;
    const int j = tid & 31;
    const int b = blockIdx.x * WARPS_PER_CTA + w;

    // zero h state (both parities)
    for (int q = tid; q < WARPS_PER_CTA * 3 * 2 * HDIM; q += WARPS_PER_CTA * 32)
        (&hb[0][0][0][0])[q] = 0.0f;
    __syncthreads();

    // ---- load weights into per-lane registers as packed f32x2 pairs ----
    ull wx0[3], wr0[16], wp1[16], wr1[16], wp2[16], wr2[16];
    {
        const ull* q = reinterpret_cast<const ull*>(Wih0 + j * DIN);    // j*24B: 8B aligned
        wx0[0] = q[0]; wx0[1] = q[1]; wx0[2] = q[2];
    }
    {
        const ull* q0 = reinterpret_cast<const ull*>(Whh  + (0 * HDIM + j) * HDIM);
        const ull* q1 = reinterpret_cast<const ull*>(Whh  + (1 * HDIM + j) * HDIM);
        const ull* q2 = reinterpret_cast<const ull*>(Whh  + (2 * HDIM + j) * HDIM);
        const ull* p1 = reinterpret_cast<const ull*>(WihR + (0 * HDIM + j) * HDIM);
        const ull* p2 = reinterpret_cast<const ull*>(WihR + (1 * HDIM + j) * HDIM);
#pragma unroll
        for (int k = 0; k < 16; k++) {
            wr0[k] = q0[k]; wr1[k] = q1[k]; wr2[k] = q2[k];
            wp1[k] = p1[k]; wp2[k] = p2[k];
        }
    }
    const ull bp0 = pack2(bih[0 * HDIM + j] + bhh[0 * HDIM + j], 0.0f);
    const ull bp1 = pack2(bih[1 * HDIM + j] + bhh[1 * HDIM + j], 0.0f);
    const ull bp2 = pack2(bih[2 * HDIM + j] + bhh[2 * HDIM + j], 0.0f);

    float* h0 = &hb[w][0][0][0];
    float* h1 = &hb[w][1][0][0];
    float* h2 = &hb[w][2][0][0];

    // ---- x staging: chunk 0 direct, chunk 1 prefetched into registers ----
    const float4* gx = reinterpret_cast<const float4*>(x + (size_t)b * (T_STEPS * DIN));
    float4* xs0 = reinterpret_cast<float4*>(&xs[w][0][0]);
    float4* xs1 = reinterpret_cast<float4*>(&xs[w][1][0]);

    xs0[j] = gx[j]; xs0[j + 32] = gx[j + 32]; xs0[j + 64] = gx[j + 64];
    CBAR();
    float4 pf0 = gx[96 + j], pf1 = gx[96 + j + 32], pf2 = gx[96 + j + 64];

    float h2last = 0.0f;

    // one skewed iteration: L0 at t=i, L1 at t=i-1, L2 at t=i-2 (mutually independent)
    auto iter = [&](int pw, const float* xp) {
        const int pr = pw ^ 1;
        float n0 = cell0(wx0, xp,             wr0, h0 + pr * HDIM, bp0);
        float n1 = cell (wp1, h0 + pr * HDIM, wr1, h1 + pw * HDIM, bp1);
        float n2 = cell (wp2, h1 + pw * HDIM, wr2, h2 + pr * HDIM, bp2);
        h0[pw * HDIM + j] = n0;
        h1[pr * HDIM + j] = n1;
        h2[pw * HDIM + j] = n2;
        CBAR();                                  // compiler fence only; HW smem is in-order per warp
    };

    // ---- prologue peels ----
    {   // i = 0: only L0(0); h0[-1]=0 (parity 1 zeroed)
        float n0 = cell0(wx0, &xs[w][0][0 * DIN], wr0, h0 + HDIM, bp0);
        h0[j] = n0;
        CBAR();
    }
    {   // i = 1: L0(1) + L1(0); h1[-1]=0 (parity 1 zeroed)
        float n0 = cell0(wx0, &xs[w][0][1 * DIN], wr0, h0, bp0);
        float n1 = cell (wp1, h0, wr1, h1 + HDIM, bp1);
        h0[HDIM + j] = n0;
        h1[j] = n1;
        CBAR();
    }

    // ---- main loop: i = 2 .. 2047 ----
#pragma unroll 1
    for (int c = 0; c < NCHUNK; c++) {
        if (c > 0) {
            float4* dst = (c & 1) ? xs1 : xs0;
            dst[j] = pf0; dst[j + 32] = pf1; dst[j + 64] = pf2;
            CBAR();
            if (c < NCHUNK - 1) {
                pf0 = gx[(c + 1) * 96 + j];
                pf1 = gx[(c + 1) * 96 + j + 32];
                pf2 = gx[(c + 1) * 96 + j + 64];
            }
        }
        const float* xrow = (c & 1) ? &xs[w][1][0] : &xs[w][0][0];
        const int s0 = (c == 0) ? 2 : 0;
#pragma unroll 1
        for (int s = s0; s < CHUNK; s += 2) {
            iter(0, xrow + s * DIN);            // even global t
            iter(1, xrow + (s + 1) * DIN);      // odd global t
        }
    }

    // ---- epilogue peels ----
    {   // i = 2048 (pw=0, pr=1): L1(2047) + L2(2046)
        float n1 = cell(wp1, h0 + HDIM, wr1, h1,        bp1);
        float n2 = cell(wp2, h1,        wr2, h2 + HDIM, bp2);
        h1[HDIM + j] = n1;
        h2[j] = n2;
        CBAR();
    }
    {   // i = 2049 (pw=1, pr=0): L2(2047) -> final hidden state, keep in register
        h2last = cell(wp2, h1 + HDIM, wr2, h2, bp2);
    }

    // ---- FC head: out[b,c] = sum_j h2last_j * fcw[c,j] + fcb[c] ----
    float s0v = h2last * fcw[0 * HDIM + j];
    float s1v = h2last * fcw[1 * HDIM + j];
    float s2v = h2last * fcw[2 * HDIM + j];
    float s3v = h2last * fcw[3 * HDIM + j];
    float s4v = h2last * fcw[4 * HDIM + j];
    float s5v = h2last * fcw[5 * HDIM + j];
#pragma unroll
    for (int off = 16; off; off >>= 1) {
        s0v += __shfl_xor_sync(0xffffffffu, s0v, off);
        s1v += __shfl_xor_sync(0xffffffffu, s1v, off);
        s2v += __shfl_xor_sync(0xffffffffu, s2v, off);
        s3v += __shfl_xor_sync(0xffffffffu, s3v, off);
        s4v += __shfl_xor_sync(0xffffffffu, s4v, off);
        s5v += __shfl_xor_sync(0xffffffffu, s5v, off);
    }
    float v = s0v;
    if (j == 1) v = s1v;
    if (j == 2) v = s2v;
    if (j == 3) v = s3v;
    if (j == 4) v = s4v;
    if (j == 5) v = s5v;
    if (j < 6) out[b * 6 + j] = v + fcb[j];
}

extern "C" void kernel_launch(void* const* d_in, const int* in_sizes, int n_in,
                              void* d_out, int out_size) {
    const float* x    = (const float*)d_in[0];
    const float* Wih0 = (const float*)d_in[1];
    const float* WihR = (const float*)d_in[2];
    const float* Whh  = (const float*)d_in[3];
    const float* bih  = (const float*)d_in[4];
    const float* bhh  = (const float*)d_in[5];
    const float* fcw  = (const float*)d_in[6];
    const float* fcb  = (const float*)d_in[7];

    const int B = in_sizes[0] / (T_STEPS * DIN);   // 512
    rnn3_fused_kernel<<<B / WARPS_PER_CTA, WARPS_PER_CTA * 32>>>(
        x, Wih0, WihR, Whh, bih, bhh, fcw, fcb, (float*)d_out);
}

// round 11
// speedup vs baseline: 1.9507x; 1.0096x over previous
#include <cuda_runtime.h>
#include <cstdint>
#include <cstddef>

typedef unsigned long long ull;

#define T_STEPS 2048
#define HDIM 32
#define DIN 6
#define WARPS_PER_CTA 4
#define CHUNK 64
#define NCHUNK (T_STEPS / CHUNK)

// Compiler-only memory fence (no instruction). Used ONLY at x-chunk staging
// boundaries; per-iteration ordering is guaranteed by per-thread aliasing
// (each lane's h-vector load overlaps its own store) + warp in-order smem.
#define CBAR() asm volatile("" ::: "memory")

__device__ __forceinline__ ull fma2(ull a, ull b, ull c) {
    ull r;
    asm("fma.rn.f32x2 %0, %1, %2, %3;" : "=l"(r) : "l"(a), "l"(b), "l"(c));
    return r;
}
__device__ __forceinline__ ull add2(ull a, ull b) {
    ull r;
    asm("add.rn.f32x2 %0, %1, %2;" : "=l"(r) : "l"(a), "l"(b));
    return r;
}
__device__ __forceinline__ float hsum2(ull a) {
    float lo, hi;
    asm("mov.b64 {%0, %1}, %2;" : "=f"(lo), "=f"(hi) : "l"(a));
    return lo + hi;
}
__device__ __forceinline__ ull pack2(float lo, float hi) {
    ull r;
    asm("mov.b64 %0, {%1, %2};" : "=l"(r) : "f"(lo), "f"(hi));
    return r;
}
// single-instruction MUFU.TANH
__device__ __forceinline__ float tanh_mufu(float x) {
    float r;
    asm("tanh.approx.f32 %0, %1;" : "=f"(r) : "f"(x));
    return r;
}

// RNN cell (layers 1,2): tanh( Wp . hin + Wr . hprev + bias ), bias folded into a0 init
__device__ __forceinline__ float cell(const ull (&wp)[16], const float* hin,
                                      const ull (&wr)[16], const float* hprev,
                                      ull biasp) {
    ull a0 = biasp, a1 = 0ull, a2 = 0ull, a3 = 0ull;
    const ulonglong2* hp = reinterpret_cast<const ulonglong2*>(hin);
    const ulonglong2* hr = reinterpret_cast<const ulonglong2*>(hprev);
#pragma unroll
    for (int p = 0; p < 8; p++) {
        ulonglong2 u = hp[p];           // LDS.128 broadcast: h[4p..4p+3]
        a0 = fma2(u.x, wp[2 * p],     a0);
        a1 = fma2(u.y, wp[2 * p + 1], a1);
        ulonglong2 v = hr[p];
        a2 = fma2(v.x, wr[2 * p],     a2);
        a3 = fma2(v.y, wr[2 * p + 1], a3);
    }
    a0 = add2(add2(a0, a1), add2(a2, a3));
    return tanh_mufu(hsum2(a0));
}

// layer-0 cell: x-projection (D=6 -> 3 pairs) + recurrence, bias folded
__device__ __forceinline__ float cell0(const ull (&wx)[3], const float* xp,
                                       const ull (&wr)[16], const float* hprev,
                                       ull biasp) {
    const ull* xq = reinterpret_cast<const ull*>(xp);   // 8B-aligned pairs
    ull a0 = fma2(xq[0], wx[0], biasp);
    a0 = fma2(xq[1], wx[1], a0);
    a0 = fma2(xq[2], wx[2], a0);
    ull a1 = 0ull, a2 = 0ull;
    const ulonglong2* hr = reinterpret_cast<const ulonglong2*>(hprev);
#pragma unroll
    for (int p = 0; p < 8; p++) {
        ulonglong2 v = hr[p];
        a1 = fma2(v.x, wr[2 * p],     a1);
        a2 = fma2(v.y, wr[2 * p + 1], a2);
    }
    a0 = add2(a0, add2(a1, a2));
    return tanh_mufu(hsum2(a0));
}

__global__ void __launch_bounds__(WARPS_PER_CTA * 32, 1)
rnn3_fused_kernel(const float* __restrict__ x,
                  const float* __restrict__ Wih0,
                  const float* __restrict__ WihR,
                  const float* __restrict__ Whh,
                  const float* __restrict__ bih,
                  const float* __restrict__ bhh,
                  const float* __restrict__ fcw,
                  const float* __restrict__ fcb,
                  float* __restrict__ out) {
    __shared__ __align__(16) float hb[WARPS_PER_CTA][3][2][HDIM];       // [warp][layer][parity][h]
    __shared__ __align__(16) float xs[WARPS_PER_CTA][2][CHUNK * DIN];   // x staging, double buffered

    const int tid = threadIdx.x;
    const int w = tid >> 5;
    const int j = tid & 31;
    const int b = blockIdx.x * WARPS_PER_CTA + w;

    // zero h state (both parities)
    for (int q = tid; q < WARPS_PER_CTA * 3 * 2 * HDIM; q += WARPS_PER_CTA * 32)
        (&hb[0][0][0][0])[q] = 0.0f;
    __syncthreads();

    // ---- load weights into per-lane registers as packed f32x2 pairs ----
    ull wx0[3], wr0[16], wp1[16], wr1[16], wp2[16], wr2[16];
    {
        const ull* q = reinterpret_cast<const ull*>(Wih0 + j * DIN);    // j*24B: 8B aligned
        wx0[0] = q[0]; wx0[1] = q[1]; wx0[2] = q[2];
    }
    {
        const ull* q0 = reinterpret_cast<const ull*>(Whh  + (0 * HDIM + j) * HDIM);
        const ull* q1 = reinterpret_cast<const ull*>(Whh  + (1 * HDIM + j) * HDIM);
        const ull* q2 = reinterpret_cast<const ull*>(Whh  + (2 * HDIM + j) * HDIM);
        const ull* p1 = reinterpret_cast<const ull*>(WihR + (0 * HDIM + j) * HDIM);
        const ull* p2 = reinterpret_cast<const ull*>(WihR + (1 * HDIM + j) * HDIM);
#pragma unroll
        for (int k = 0; k < 16; k++) {
            wr0[k] = q0[k]; wr1[k] = q1[k]; wr2[k] = q2[k];
            wp1[k] = p1[k]; wp2[k] = p2[k];
        }
    }
    const ull bp0 = pack2(bih[0 * HDIM + j] + bhh[0 * HDIM + j], 0.0f);
    const ull bp1 = pack2(bih[1 * HDIM + j] + bhh[1 * HDIM + j], 0.0f);
    const ull bp2 = pack2(bih[2 * HDIM + j] + bhh[2 * HDIM + j], 0.0f);

    float* h0 = &hb[w][0][0][0];
    float* h1 = &hb[w][1][0][0];
    float* h2 = &hb[w][2][0][0];

    // ---- x staging: chunk 0 direct, chunk 1 prefetched into registers ----
    const float4* gx = reinterpret_cast<const float4*>(x + (size_t)b * (T_STEPS * DIN));
    float4* xs0 = reinterpret_cast<float4*>(&xs[w][0][0]);
    float4* xs1 = reinterpret_cast<float4*>(&xs[w][1][0]);

    xs0[j] = gx[j]; xs0[j + 32] = gx[j + 32]; xs0[j + 64] = gx[j + 64];
    CBAR();
    float4 pf0 = gx[96 + j], pf1 = gx[96 + j + 32], pf2 = gx[96 + j + 64];

    float h2last = 0.0f;

    // one skewed iteration: L0 at t=i, L1 at t=i-1, L2 at t=i-2.
    // No fence at the end: per-thread aliasing (each lane's vector load
    // overlaps its own store) already orders store->load; disjoint-parity
    // ops may be freely pipelined across iterations by ptxas.
    auto iter = [&](int pw, const float* xp) {
        const int pr = pw ^ 1;
        float n0 = cell0(wx0, xp,             wr0, h0 + pr * HDIM, bp0);
        float n1 = cell (wp1, h0 + pr * HDIM, wr1, h1 + pw * HDIM, bp1);
        float n2 = cell (wp2, h1 + pw * HDIM, wr2, h2 + pr * HDIM, bp2);
        h0[pw * HDIM + j] = n0;
        h1[pr * HDIM + j] = n1;
        h2[pw * HDIM + j] = n2;
    };

    // ---- prologue peels ----
    {   // i = 0: only L0(0); h0[-1]=0 (parity 1 zeroed)
        float n0 = cell0(wx0, &xs[w][0][0 * DIN], wr0, h0 + HDIM, bp0);
        h0[j] = n0;
    }
    {   // i = 1: L0(1) + L1(0); h1[-1]=0 (parity 1 zeroed)
        float n0 = cell0(wx0, &xs[w][0][1 * DIN], wr0, h0, bp0);
        float n1 = cell (wp1, h0, wr1, h1 + HDIM, bp1);
        h0[HDIM + j] = n0;
        h1[j] = n1;
    }

    // ---- chunk 0 (cold): i = 2 .. 63 ----
#pragma unroll 1
    for (int s = 2; s < CHUNK; s += 2) {
        iter(0, &xs[w][0][s * DIN]);
        iter(1, &xs[w][0][(s + 1) * DIN]);
    }

    // ---- main chunks 1 .. NCHUNK-1 (hot, unrolled x4 for cross-iter pipelining) ----
#pragma unroll 1
    for (int c = 1; c < NCHUNK; c++) {
        {   // stage chunk c from prefetch regs, prefetch chunk c+1
            float4* dst = (c & 1) ? xs1 : xs0;
            dst[j] = pf0; dst[j + 32] = pf1; dst[j + 64] = pf2;
            CBAR();
            if (c < NCHUNK - 1) {
                pf0 = gx[(c + 1) * 96 + j];
                pf1 = gx[(c + 1) * 96 + j + 32];
                pf2 = gx[(c + 1) * 96 + j + 64];
            }
        }
        const float* xrow = (c & 1) ? &xs[w][1][0] : &xs[w][0][0];
#pragma unroll 4
        for (int s = 0; s < CHUNK; s += 2) {
            iter(0, xrow + s * DIN);            // even global t
            iter(1, xrow + (s + 1) * DIN);      // odd global t
        }
        CBAR();                                  // don't float next chunk's staging stores up
    }

    // ---- epilogue peels ----
    {   // i = 2048 (pw=0, pr=1): L1(2047) + L2(2046)
        float n1 = cell(wp1, h0 + HDIM, wr1, h1,        bp1);
        float n2 = cell(wp2, h1,        wr2, h2 + HDIM, bp2);
        h1[HDIM + j] = n1;
        h2[j] = n2;
    }
    {   // i = 2049 (pw=1, pr=0): L2(2047) -> final hidden state, keep in register
        h2last = cell(wp2, h1 + HDIM, wr2, h2, bp2);
    }

    // ---- FC head: out[b,c] = sum_j h2last_j * fcw[c,j] + fcb[c] ----
    float s0v = h2last * fcw[0 * HDIM + j];
    float s1v = h2last * fcw[1 * HDIM + j];
    float s2v = h2last * fcw[2 * HDIM + j];
    float s3v = h2last * fcw[3 * HDIM + j];
    float s4v = h2last * fcw[4 * HDIM + j];
    float s5v = h2last * fcw[5 * HDIM + j];
#pragma unroll
    for (int off = 16; off; off >>= 1) {
        s0v += __shfl_xor_sync(0xffffffffu, s0v, off);
        s1v += __shfl_xor_sync(0xffffffffu, s1v, off);
        s2v += __shfl_xor_sync(0xffffffffu, s2v, off);
        s3v += __shfl_xor_sync(0xffffffffu, s3v, off);
        s4v += __shfl_xor_sync(0xffffffffu, s4v, off);
        s5v += __shfl_xor_sync(0xffffffffu, s5v, off);
    }
    float v = s0v;
    if (j == 1) v = s1v;
    if (j == 2) v = s2v;
    if (j == 3) v = s3v;
    if (j == 4) v = s4v;
    if (j == 5) v = s5v;
    if (j < 6) out[b * 6 + j] = v + fcb[j];
}

extern "C" void kernel_launch(void* const* d_in, const int* in_sizes, int n_in,
                              void* d_out, int out_size) {
    const float* x    = (const float*)d_in[0];
    const float* Wih0 = (const float*)d_in[1];
    const float* WihR = (const float*)d_in[2];
    const float* Whh  = (const float*)d_in[3];
    const float* bih  = (const float*)d_in[4];
    const float* bhh  = (const float*)d_in[5];
    const float* fcw  = (const float*)d_in[6];
    const float* fcb  = (const float*)d_in[7];

    const int B = in_sizes[0] / (T_STEPS * DIN);   // 512
    rnn3_fused_kernel<<<B / WARPS_PER_CTA, WARPS_PER_CTA * 32>>>(
        x, Wih0, WihR, Whh, bih, bhh, fcw, fcb, (float*)d_out);
}